// round 10
// baseline (speedup 1.0000x reference)
#include <cuda_runtime.h>
#include <math.h>

// Problem constants
#define BB   32
#define SS   512
#define HH   512
#define K4   128          // HH/4
#define MTOT (BB*SS)      // 16384
#define NBUF (MTOT*HH)    // 8388608 floats per buffer

// Scratch: 6 ping-pong buffers (f/b directions x {layer-out, conv-out, hw1-out})
__device__ float g_buf[6][NBUF];

// ---------------- packed fp32x2 helpers ----------------
#define PACK2(d, f) asm("mov.b64 %0, {%1, %1};" : "=l"(d) : "f"(f))
#define UNPACK2(lo, hi, v) asm("mov.b64 {%0, %1}, %2;" : "=f"(lo), "=f"(hi) : "l"(v))
#define FMA2(d, a, b) asm("fma.rn.f32x2 %0, %1, %2, %0;" : "+l"(d) : "l"(a), "l"(b))

// ---------------- 5-tap window conv (both directions) ----------------
// yf[b,t,:] = sum_k wf[k] * (t-4+k >= 0 ? xf[b,t-4+k,:] : fpad[t+k,:])
// yb[b,t,:] = sum_k wb[k] * (t+k   <  S ? xb[b,t+k,:]   : bpad[t+k-S,:])
__global__ void conv_kernel(const float* __restrict__ xf, const float* __restrict__ xb,
                            const float* __restrict__ fpad, const float* __restrict__ bpad,
                            const float* __restrict__ wf, const float* __restrict__ wb,
                            float* __restrict__ yf, float* __restrict__ yb)
{
    int t = blockIdx.x;
    int b = blockIdx.y;
    int h4 = threadIdx.x;                 // 0..127 (float4 lanes over H)

    float4 af = make_float4(0.f, 0.f, 0.f, 0.f);
    float4 ab = make_float4(0.f, 0.f, 0.f, 0.f);

#pragma unroll
    for (int k = 0; k <= 4; ++k) {
        float wfk = wf[k];
        int sf = t - 4 + k;
        const float4* pf = (sf >= 0)
            ? ((const float4*)xf) + (size_t)(b * SS + sf) * K4
            : ((const float4*)fpad) + (size_t)(t + k) * K4;
        float4 v = pf[h4];
        af.x += wfk * v.x; af.y += wfk * v.y; af.z += wfk * v.z; af.w += wfk * v.w;

        float wbk = wb[k];
        int sb = t + k;
        const float4* pb = (sb < SS)
            ? ((const float4*)xb) + (size_t)(b * SS + sb) * K4
            : ((const float4*)bpad) + (size_t)(sb - SS) * K4;
        float4 u = pb[h4];
        ab.x += wbk * u.x; ab.y += wbk * u.y; ab.z += wbk * u.z; ab.w += wbk * u.w;
    }

    int o = (b * SS + t) * K4 + h4;
    ((float4*)yf)[o] = af;
    ((float4*)yb)[o] = ab;
}

// ---------------- fused highway GEMM ----------------
// proj[m, o] = sum_h X[m,h] * W[o,h] + bias[o],  o in [0,2H)
// nonlin = relu(proj[:, :H]); gate = sigmoid(proj[:, H:])
// Y[m,h] = gate*X[m,h] + (1-gate)*nonlin
// CTA tile: 128 rows x 64 cols of BOTH halves (cols n0..n0+63 and 512+n0..).
// blockIdx.z selects direction (0=fwd, 1=bwd).
__global__ void __launch_bounds__(256, 2)
hw_gemm(const float* __restrict__ Xf, const float* __restrict__ Xb,
        const float* __restrict__ Wf, const float* __restrict__ Wb,
        const float* __restrict__ Bf, const float* __restrict__ Bb,
        float* __restrict__ Yf, float* __restrict__ Yb,
        float* __restrict__ out2)   // optional d_out slice (layer base), may be null
{
    int dir = blockIdx.z;
    const float* X    = dir ? Xb : Xf;
    const float* Wt   = dir ? Wb : Wf;
    const float* bias = dir ? Bb : Bf;
    float*       Y    = dir ? Yb : Yf;

    __shared__ float As[16][132];   // [k][m], padded to kill STS conflicts
    __shared__ float Bs[16][132];   // [k][o_local]: 0..63 nonlin, 64..127 gate

    int tid = threadIdx.x;
    int tx = tid & 15;              // col group  (4 cols per half)
    int ty = tid >> 4;              // row group  (8 rows)
    int n0 = blockIdx.x << 6;       // *64
    int m0 = blockIdx.y << 7;       // *128

    // global tile loaders: each thread loads 2 consecutive float4 of one row
    int lrow = tid >> 1;                         // 0..127
    int lc   = (tid & 1) << 1;                   // 0 or 2 (float4 index within 16-float row)
    int grow = (lrow < 64) ? (n0 + lrow) : (512 + n0 + lrow - 64);

    const float4* X4 = (const float4*)X;
    const float4* W4 = (const float4*)Wt;
    int aBase = (m0 + lrow) * K4 + lc;
    int bBase = grow * K4 + lc;

    unsigned long long aN[8][2], aG[8][2];       // f32x2 accumulators
#pragma unroll
    for (int r = 0; r < 8; ++r) { aN[r][0] = aN[r][1] = aG[r][0] = aG[r][1] = 0ull; }

    for (int k0 = 0; k0 < K4; k0 += 4) {         // 32 iterations of BK=16
        float4 a0 = X4[aBase + k0];
        float4 a1 = X4[aBase + k0 + 1];
        float4 b0 = W4[bBase + k0];
        float4 b1 = W4[bBase + k0 + 1];

        __syncthreads();                         // previous compute done
        int c4 = lc << 2;
        As[c4 + 0][lrow] = a0.x; As[c4 + 1][lrow] = a0.y;
        As[c4 + 2][lrow] = a0.z; As[c4 + 3][lrow] = a0.w;
        As[c4 + 4][lrow] = a1.x; As[c4 + 5][lrow] = a1.y;
        As[c4 + 6][lrow] = a1.z; As[c4 + 7][lrow] = a1.w;
        Bs[c4 + 0][lrow] = b0.x; Bs[c4 + 1][lrow] = b0.y;
        Bs[c4 + 2][lrow] = b0.z; Bs[c4 + 3][lrow] = b0.w;
        Bs[c4 + 4][lrow] = b1.x; Bs[c4 + 5][lrow] = b1.y;
        Bs[c4 + 6][lrow] = b1.z; Bs[c4 + 7][lrow] = b1.w;
        __syncthreads();

#pragma unroll
        for (int k = 0; k < 16; ++k) {
            float4 af0 = *(const float4*)&As[k][ty * 8];
            float4 af1 = *(const float4*)&As[k][ty * 8 + 4];
            unsigned long long ad[8];
            PACK2(ad[0], af0.x); PACK2(ad[1], af0.y);
            PACK2(ad[2], af0.z); PACK2(ad[3], af0.w);
            PACK2(ad[4], af1.x); PACK2(ad[5], af1.y);
            PACK2(ad[6], af1.z); PACK2(ad[7], af1.w);

            ulonglong2 bn = *(const ulonglong2*)&Bs[k][tx * 4];
            ulonglong2 bg = *(const ulonglong2*)&Bs[k][64 + tx * 4];

#pragma unroll
            for (int r = 0; r < 8; ++r) {
                FMA2(aN[r][0], ad[r], bn.x);
                FMA2(aN[r][1], ad[r], bn.y);
                FMA2(aG[r][0], ad[r], bg.x);
                FMA2(aG[r][1], ad[r], bg.y);
            }
        }
    }

    // ---- epilogue: bias + relu/sigmoid + highway blend + stores ----
    float4 bn4 = *(const float4*)(bias + n0 + tx * 4);
    float4 bg4 = *(const float4*)(bias + 512 + n0 + tx * 4);
    int colBase = (n0 >> 2) + tx;

#pragma unroll
    for (int r = 0; r < 8; ++r) {
        int m = m0 + ty * 8 + r;
        float p0, p1, p2, p3, g0, g1, g2, g3;
        UNPACK2(p0, p1, aN[r][0]); UNPACK2(p2, p3, aN[r][1]);
        UNPACK2(g0, g1, aG[r][0]); UNPACK2(g2, g3, aG[r][1]);

        p0 = fmaxf(p0 + bn4.x, 0.f); p1 = fmaxf(p1 + bn4.y, 0.f);
        p2 = fmaxf(p2 + bn4.z, 0.f); p3 = fmaxf(p3 + bn4.w, 0.f);
        g0 = 1.f / (1.f + __expf(-(g0 + bg4.x)));
        g1 = 1.f / (1.f + __expf(-(g1 + bg4.y)));
        g2 = 1.f / (1.f + __expf(-(g2 + bg4.z)));
        g3 = 1.f / (1.f + __expf(-(g3 + bg4.w)));

        float4 xin = X4[m * K4 + colBase];
        float4 y;
        y.x = g0 * xin.x + (1.f - g0) * p0;
        y.y = g1 * xin.y + (1.f - g1) * p1;
        y.z = g2 * xin.z + (1.f - g2) * p2;
        y.w = g3 * xin.w + (1.f - g3) * p3;

        ((float4*)Y)[m * K4 + colBase] = y;
        if (out2) {
            // d_out row stride 2H=1024 floats = 256 float4; fwd cols [0,512), bwd [512,1024)
            ((float4*)out2)[m * 256 + dir * 128 + colBase] = y;
        }
    }
}

// ---------------- launcher ----------------
extern "C" void kernel_launch(void* const* d_in, const int* in_sizes, int n_in,
                              void* d_out, int out_size)
{
    const float* in   = (const float*)d_in[0];
    // d_in[1] = masks (unused, matching reference)
    const float* fpad = (const float*)d_in[2];
    const float* bpad = (const float*)d_in[3];
    const float* fws  = (const float*)d_in[4];
    const float* bws  = (const float*)d_in[5];
    const float* fW   = (const float*)d_in[6];
    const float* fb   = (const float*)d_in[7];
    const float* bW   = (const float*)d_in[8];
    const float* bb   = (const float*)d_in[9];
    float* out = (float*)d_out;

    void* sym = nullptr;
    cudaGetSymbolAddress(&sym, g_buf);
    float* base = (float*)sym;
    float* b_[6];
    for (int i = 0; i < 6; ++i) b_[i] = base + (size_t)i * NBUF;

    dim3 cgrid(SS, BB);
    dim3 ggrid(8, MTOT / 128, 2);

    for (int l = 0; l < 2; ++l) {
        const float* xf = l ? b_[0] : in;
        const float* xb = l ? b_[1] : in;
        conv_kernel<<<cgrid, 128>>>(xf, xb,
                                    fpad + (size_t)l * 4 * HH, bpad + (size_t)l * 4 * HH,
                                    fws + l * 5, bws + l * 5,
                                    b_[2], b_[3]);

        size_t w0 = (size_t)(l * 2) * 1024 * 512;
        size_t w1 = (size_t)(l * 2 + 1) * 1024 * 512;

        // highway step 0: conv-out -> hw1-out
        hw_gemm<<<ggrid, 256>>>(b_[2], b_[3], fW + w0, bW + w0,
                                fb + (size_t)(l * 2) * 1024, bb + (size_t)(l * 2) * 1024,
                                b_[4], b_[5], nullptr);
        // highway step 1: hw1-out -> layer-out (+ d_out slice for this layer)
        hw_gemm<<<ggrid, 256>>>(b_[4], b_[5], fW + w1, bW + w1,
                                fb + (size_t)(l * 2 + 1) * 1024, bb + (size_t)(l * 2 + 1) * 1024,
                                b_[0], b_[1], out + (size_t)l * MTOT * 1024);
    }
}

// round 11
// speedup vs baseline: 1.0002x; 1.0002x over previous
#include <cuda_runtime.h>
#include <math.h>

// Problem constants
#define BB   32
#define SS   512
#define HH   512
#define K4   128          // HH/4
#define MTOT (BB*SS)      // 16384
#define NBUF (MTOT*HH)    // 8388608 floats per buffer

// Scratch: 6 ping-pong buffers (f/b directions x {layer-out, conv-out, hw1-out})
__device__ float g_buf[6][NBUF];

// ---------------- packed fp32x2 helpers ----------------
#define PACK2(d, f) asm("mov.b64 %0, {%1, %1};" : "=l"(d) : "f"(f))
#define UNPACK2(lo, hi, v) asm("mov.b64 {%0, %1}, %2;" : "=f"(lo), "=f"(hi) : "l"(v))
#define FMA2(d, a, b) asm("fma.rn.f32x2 %0, %1, %2, %0;" : "+l"(d) : "l"(a), "l"(b))

// ---------------- 5-tap window conv (both directions) ----------------
// yf[b,t,:] = sum_k wf[k] * (t-4+k >= 0 ? xf[b,t-4+k,:] : fpad[t+k,:])
// yb[b,t,:] = sum_k wb[k] * (t+k   <  S ? xb[b,t+k,:]   : bpad[t+k-S,:])
__global__ void conv_kernel(const float* __restrict__ xf, const float* __restrict__ xb,
                            const float* __restrict__ fpad, const float* __restrict__ bpad,
                            const float* __restrict__ wf, const float* __restrict__ wb,
                            float* __restrict__ yf, float* __restrict__ yb)
{
    int t = blockIdx.x;
    int b = blockIdx.y;
    int h4 = threadIdx.x;                 // 0..127 (float4 lanes over H)

    float4 af = make_float4(0.f, 0.f, 0.f, 0.f);
    float4 ab = make_float4(0.f, 0.f, 0.f, 0.f);

#pragma unroll
    for (int k = 0; k <= 4; ++k) {
        float wfk = wf[k];
        int sf = t - 4 + k;
        const float4* pf = (sf >= 0)
            ? ((const float4*)xf) + (size_t)(b * SS + sf) * K4
            : ((const float4*)fpad) + (size_t)(t + k) * K4;
        float4 v = pf[h4];
        af.x += wfk * v.x; af.y += wfk * v.y; af.z += wfk * v.z; af.w += wfk * v.w;

        float wbk = wb[k];
        int sb = t + k;
        const float4* pb = (sb < SS)
            ? ((const float4*)xb) + (size_t)(b * SS + sb) * K4
            : ((const float4*)bpad) + (size_t)(sb - SS) * K4;
        float4 u = pb[h4];
        ab.x += wbk * u.x; ab.y += wbk * u.y; ab.z += wbk * u.z; ab.w += wbk * u.w;
    }

    int o = (b * SS + t) * K4 + h4;
    ((float4*)yf)[o] = af;
    ((float4*)yb)[o] = ab;
}

// ---------------- fused highway GEMM ----------------
// proj[m, o] = sum_h X[m,h] * W[o,h] + bias[o],  o in [0,2H)
// nonlin = relu(proj[:, :H]); gate = sigmoid(proj[:, H:])
// Y[m,h] = gate*X[m,h] + (1-gate)*nonlin
// CTA tile: 128 rows x 64 cols of BOTH halves (cols n0..n0+63 and 512+n0..).
// blockIdx.z selects direction (0=fwd, 1=bwd).
__global__ void __launch_bounds__(256, 2)
hw_gemm(const float* __restrict__ Xf, const float* __restrict__ Xb,
        const float* __restrict__ Wf, const float* __restrict__ Wb,
        const float* __restrict__ Bf, const float* __restrict__ Bb,
        float* __restrict__ Yf, float* __restrict__ Yb,
        float* __restrict__ out2)   // optional d_out slice (layer base), may be null
{
    int dir = blockIdx.z;
    const float* X    = dir ? Xb : Xf;
    const float* Wt   = dir ? Wb : Wf;
    const float* bias = dir ? Bb : Bf;
    float*       Y    = dir ? Yb : Yf;

    __shared__ float As[16][132];   // [k][m], padded to kill STS conflicts
    __shared__ float Bs[16][132];   // [k][o_local]: 0..63 nonlin, 64..127 gate

    int tid = threadIdx.x;
    int tx = tid & 15;              // col group  (4 cols per half)
    int ty = tid >> 4;              // row group  (8 rows)
    int n0 = blockIdx.x << 6;       // *64
    int m0 = blockIdx.y << 7;       // *128

    // global tile loaders: each thread loads 2 consecutive float4 of one row
    int lrow = tid >> 1;                         // 0..127
    int lc   = (tid & 1) << 1;                   // 0 or 2 (float4 index within 16-float row)
    int grow = (lrow < 64) ? (n0 + lrow) : (512 + n0 + lrow - 64);

    const float4* X4 = (const float4*)X;
    const float4* W4 = (const float4*)Wt;
    int aBase = (m0 + lrow) * K4 + lc;
    int bBase = grow * K4 + lc;

    unsigned long long aN[8][2], aG[8][2];       // f32x2 accumulators
#pragma unroll
    for (int r = 0; r < 8; ++r) { aN[r][0] = aN[r][1] = aG[r][0] = aG[r][1] = 0ull; }

    for (int k0 = 0; k0 < K4; k0 += 4) {         // 32 iterations of BK=16
        float4 a0 = X4[aBase + k0];
        float4 a1 = X4[aBase + k0 + 1];
        float4 b0 = W4[bBase + k0];
        float4 b1 = W4[bBase + k0 + 1];

        __syncthreads();                         // previous compute done
        int c4 = lc << 2;
        As[c4 + 0][lrow] = a0.x; As[c4 + 1][lrow] = a0.y;
        As[c4 + 2][lrow] = a0.z; As[c4 + 3][lrow] = a0.w;
        As[c4 + 4][lrow] = a1.x; As[c4 + 5][lrow] = a1.y;
        As[c4 + 6][lrow] = a1.z; As[c4 + 7][lrow] = a1.w;
        Bs[c4 + 0][lrow] = b0.x; Bs[c4 + 1][lrow] = b0.y;
        Bs[c4 + 2][lrow] = b0.z; Bs[c4 + 3][lrow] = b0.w;
        Bs[c4 + 4][lrow] = b1.x; Bs[c4 + 5][lrow] = b1.y;
        Bs[c4 + 6][lrow] = b1.z; Bs[c4 + 7][lrow] = b1.w;
        __syncthreads();

#pragma unroll
        for (int k = 0; k < 16; ++k) {
            float4 af0 = *(const float4*)&As[k][ty * 8];
            float4 af1 = *(const float4*)&As[k][ty * 8 + 4];
            unsigned long long ad[8];
            PACK2(ad[0], af0.x); PACK2(ad[1], af0.y);
            PACK2(ad[2], af0.z); PACK2(ad[3], af0.w);
            PACK2(ad[4], af1.x); PACK2(ad[5], af1.y);
            PACK2(ad[6], af1.z); PACK2(ad[7], af1.w);

            ulonglong2 bn = *(const ulonglong2*)&Bs[k][tx * 4];
            ulonglong2 bg = *(const ulonglong2*)&Bs[k][64 + tx * 4];

#pragma unroll
            for (int r = 0; r < 8; ++r) {
                FMA2(aN[r][0], ad[r], bn.x);
                FMA2(aN[r][1], ad[r], bn.y);
                FMA2(aG[r][0], ad[r], bg.x);
                FMA2(aG[r][1], ad[r], bg.y);
            }
        }
    }

    // ---- epilogue: bias + relu/sigmoid + highway blend + stores ----
    float4 bn4 = *(const float4*)(bias + n0 + tx * 4);
    float4 bg4 = *(const float4*)(bias + 512 + n0 + tx * 4);
    int colBase = (n0 >> 2) + tx;

#pragma unroll
    for (int r = 0; r < 8; ++r) {
        int m = m0 + ty * 8 + r;
        float p0, p1, p2, p3, g0, g1, g2, g3;
        UNPACK2(p0, p1, aN[r][0]); UNPACK2(p2, p3, aN[r][1]);
        UNPACK2(g0, g1, aG[r][0]); UNPACK2(g2, g3, aG[r][1]);

        p0 = fmaxf(p0 + bn4.x, 0.f); p1 = fmaxf(p1 + bn4.y, 0.f);
        p2 = fmaxf(p2 + bn4.z, 0.f); p3 = fmaxf(p3 + bn4.w, 0.f);
        g0 = 1.f / (1.f + __expf(-(g0 + bg4.x)));
        g1 = 1.f / (1.f + __expf(-(g1 + bg4.y)));
        g2 = 1.f / (1.f + __expf(-(g2 + bg4.z)));
        g3 = 1.f / (1.f + __expf(-(g3 + bg4.w)));

        float4 xin = X4[m * K4 + colBase];
        float4 y;
        y.x = g0 * xin.x + (1.f - g0) * p0;
        y.y = g1 * xin.y + (1.f - g1) * p1;
        y.z = g2 * xin.z + (1.f - g2) * p2;
        y.w = g3 * xin.w + (1.f - g3) * p3;

        ((float4*)Y)[m * K4 + colBase] = y;
        if (out2) {
            // d_out row stride 2H=1024 floats = 256 float4; fwd cols [0,512), bwd [512,1024)
            ((float4*)out2)[m * 256 + dir * 128 + colBase] = y;
        }
    }
}

// ---------------- launcher ----------------
extern "C" void kernel_launch(void* const* d_in, const int* in_sizes, int n_in,
                              void* d_out, int out_size)
{
    const float* in   = (const float*)d_in[0];
    // d_in[1] = masks (unused, matching reference)
    const float* fpad = (const float*)d_in[2];
    const float* bpad = (const float*)d_in[3];
    const float* fws  = (const float*)d_in[4];
    const float* bws  = (const float*)d_in[5];
    const float* fW   = (const float*)d_in[6];
    const float* fb   = (const float*)d_in[7];
    const float* bW   = (const float*)d_in[8];
    const float* bb   = (const float*)d_in[9];
    float* out = (float*)d_out;

    void* sym = nullptr;
    cudaGetSymbolAddress(&sym, g_buf);
    float* base = (float*)sym;
    float* b_[6];
    for (int i = 0; i < 6; ++i) b_[i] = base + (size_t)i * NBUF;

    dim3 cgrid(SS, BB);
    dim3 ggrid(8, MTOT / 128, 2);

    for (int l = 0; l < 2; ++l) {
        const float* xf = l ? b_[0] : in;
        const float* xb = l ? b_[1] : in;
        conv_kernel<<<cgrid, 128>>>(xf, xb,
                                    fpad + (size_t)l * 4 * HH, bpad + (size_t)l * 4 * HH,
                                    fws + l * 5, bws + l * 5,
                                    b_[2], b_[3]);

        size_t w0 = (size_t)(l * 2) * 1024 * 512;
        size_t w1 = (size_t)(l * 2 + 1) * 1024 * 512;

        // highway step 0: conv-out -> hw1-out
        hw_gemm<<<ggrid, 256>>>(b_[2], b_[3], fW + w0, bW + w0,
                                fb + (size_t)(l * 2) * 1024, bb + (size_t)(l * 2) * 1024,
                                b_[4], b_[5], nullptr);
        // highway step 1: hw1-out -> layer-out (+ d_out slice for this layer)
        hw_gemm<<<ggrid, 256>>>(b_[4], b_[5], fW + w1, bW + w1,
                                fb + (size_t)(l * 2 + 1) * 1024, bb + (size_t)(l * 2 + 1) * 1024,
                                b_[0], b_[1], out + (size_t)l * MTOT * 1024);
    }
}

// round 12
// speedup vs baseline: 1.0004x; 1.0002x over previous
#include <cuda_runtime.h>
#include <math.h>

// Problem constants
#define BB   32
#define SS   512
#define HH   512
#define K4   128          // HH/4
#define MTOT (BB*SS)      // 16384
#define NBUF (MTOT*HH)    // 8388608 floats per buffer

// Scratch: 6 ping-pong buffers (f/b directions x {layer-out, conv-out, hw1-out})
__device__ float g_buf[6][NBUF];

// ---------------- packed fp32x2 helpers ----------------
#define PACK2(d, f) asm("mov.b64 %0, {%1, %1};" : "=l"(d) : "f"(f))
#define UNPACK2(lo, hi, v) asm("mov.b64 {%0, %1}, %2;" : "=f"(lo), "=f"(hi) : "l"(v))
#define FMA2(d, a, b) asm("fma.rn.f32x2 %0, %1, %2, %0;" : "+l"(d) : "l"(a), "l"(b))

// ---------------- 5-tap window conv (both directions) ----------------
// yf[b,t,:] = sum_k wf[k] * (t-4+k >= 0 ? xf[b,t-4+k,:] : fpad[t+k,:])
// yb[b,t,:] = sum_k wb[k] * (t+k   <  S ? xb[b,t+k,:]   : bpad[t+k-S,:])
__global__ void conv_kernel(const float* __restrict__ xf, const float* __restrict__ xb,
                            const float* __restrict__ fpad, const float* __restrict__ bpad,
                            const float* __restrict__ wf, const float* __restrict__ wb,
                            float* __restrict__ yf, float* __restrict__ yb)
{
    int t = blockIdx.x;
    int b = blockIdx.y;
    int h4 = threadIdx.x;                 // 0..127 (float4 lanes over H)

    float4 af = make_float4(0.f, 0.f, 0.f, 0.f);
    float4 ab = make_float4(0.f, 0.f, 0.f, 0.f);

#pragma unroll
    for (int k = 0; k <= 4; ++k) {
        float wfk = wf[k];
        int sf = t - 4 + k;
        const float4* pf = (sf >= 0)
            ? ((const float4*)xf) + (size_t)(b * SS + sf) * K4
            : ((const float4*)fpad) + (size_t)(t + k) * K4;
        float4 v = pf[h4];
        af.x += wfk * v.x; af.y += wfk * v.y; af.z += wfk * v.z; af.w += wfk * v.w;

        float wbk = wb[k];
        int sb = t + k;
        const float4* pb = (sb < SS)
            ? ((const float4*)xb) + (size_t)(b * SS + sb) * K4
            : ((const float4*)bpad) + (size_t)(sb - SS) * K4;
        float4 u = pb[h4];
        ab.x += wbk * u.x; ab.y += wbk * u.y; ab.z += wbk * u.z; ab.w += wbk * u.w;
    }

    int o = (b * SS + t) * K4 + h4;
    ((float4*)yf)[o] = af;
    ((float4*)yb)[o] = ab;
}

// ---------------- fused highway GEMM ----------------
// proj[m, o] = sum_h X[m,h] * W[o,h] + bias[o],  o in [0,2H)
// nonlin = relu(proj[:, :H]); gate = sigmoid(proj[:, H:])
// Y[m,h] = gate*X[m,h] + (1-gate)*nonlin
// CTA tile: 128 rows x 64 cols of BOTH halves (cols n0..n0+63 and 512+n0..).
// blockIdx.z selects direction (0=fwd, 1=bwd).
__global__ void __launch_bounds__(256, 2)
hw_gemm(const float* __restrict__ Xf, const float* __restrict__ Xb,
        const float* __restrict__ Wf, const float* __restrict__ Wb,
        const float* __restrict__ Bf, const float* __restrict__ Bb,
        float* __restrict__ Yf, float* __restrict__ Yb,
        float* __restrict__ out2)   // optional d_out slice (layer base), may be null
{
    int dir = blockIdx.z;
    const float* X    = dir ? Xb : Xf;
    const float* Wt   = dir ? Wb : Wf;
    const float* bias = dir ? Bb : Bf;
    float*       Y    = dir ? Yb : Yf;

    __shared__ float As[16][132];   // [k][m], padded to kill STS conflicts
    __shared__ float Bs[16][132];   // [k][o_local]: 0..63 nonlin, 64..127 gate

    int tid = threadIdx.x;
    int tx = tid & 15;              // col group  (4 cols per half)
    int ty = tid >> 4;              // row group  (8 rows)
    int n0 = blockIdx.x << 6;       // *64
    int m0 = blockIdx.y << 7;       // *128

    // global tile loaders: each thread loads 2 consecutive float4 of one row
    int lrow = tid >> 1;                         // 0..127
    int lc   = (tid & 1) << 1;                   // 0 or 2 (float4 index within 16-float row)
    int grow = (lrow < 64) ? (n0 + lrow) : (512 + n0 + lrow - 64);

    const float4* X4 = (const float4*)X;
    const float4* W4 = (const float4*)Wt;
    int aBase = (m0 + lrow) * K4 + lc;
    int bBase = grow * K4 + lc;

    unsigned long long aN[8][2], aG[8][2];       // f32x2 accumulators
#pragma unroll
    for (int r = 0; r < 8; ++r) { aN[r][0] = aN[r][1] = aG[r][0] = aG[r][1] = 0ull; }

    for (int k0 = 0; k0 < K4; k0 += 4) {         // 32 iterations of BK=16
        float4 a0 = X4[aBase + k0];
        float4 a1 = X4[aBase + k0 + 1];
        float4 b0 = W4[bBase + k0];
        float4 b1 = W4[bBase + k0 + 1];

        __syncthreads();                         // previous compute done
        int c4 = lc << 2;
        As[c4 + 0][lrow] = a0.x; As[c4 + 1][lrow] = a0.y;
        As[c4 + 2][lrow] = a0.z; As[c4 + 3][lrow] = a0.w;
        As[c4 + 4][lrow] = a1.x; As[c4 + 5][lrow] = a1.y;
        As[c4 + 6][lrow] = a1.z; As[c4 + 7][lrow] = a1.w;
        Bs[c4 + 0][lrow] = b0.x; Bs[c4 + 1][lrow] = b0.y;
        Bs[c4 + 2][lrow] = b0.z; Bs[c4 + 3][lrow] = b0.w;
        Bs[c4 + 4][lrow] = b1.x; Bs[c4 + 5][lrow] = b1.y;
        Bs[c4 + 6][lrow] = b1.z; Bs[c4 + 7][lrow] = b1.w;
        __syncthreads();

#pragma unroll
        for (int k = 0; k < 16; ++k) {
            float4 af0 = *(const float4*)&As[k][ty * 8];
            float4 af1 = *(const float4*)&As[k][ty * 8 + 4];
            unsigned long long ad[8];
            PACK2(ad[0], af0.x); PACK2(ad[1], af0.y);
            PACK2(ad[2], af0.z); PACK2(ad[3], af0.w);
            PACK2(ad[4], af1.x); PACK2(ad[5], af1.y);
            PACK2(ad[6], af1.z); PACK2(ad[7], af1.w);

            ulonglong2 bn = *(const ulonglong2*)&Bs[k][tx * 4];
            ulonglong2 bg = *(const ulonglong2*)&Bs[k][64 + tx * 4];

#pragma unroll
            for (int r = 0; r < 8; ++r) {
                FMA2(aN[r][0], ad[r], bn.x);
                FMA2(aN[r][1], ad[r], bn.y);
                FMA2(aG[r][0], ad[r], bg.x);
                FMA2(aG[r][1], ad[r], bg.y);
            }
        }
    }

    // ---- epilogue: bias + relu/sigmoid + highway blend + stores ----
    float4 bn4 = *(const float4*)(bias + n0 + tx * 4);
    float4 bg4 = *(const float4*)(bias + 512 + n0 + tx * 4);
    int colBase = (n0 >> 2) + tx;

#pragma unroll
    for (int r = 0; r < 8; ++r) {
        int m = m0 + ty * 8 + r;
        float p0, p1, p2, p3, g0, g1, g2, g3;
        UNPACK2(p0, p1, aN[r][0]); UNPACK2(p2, p3, aN[r][1]);
        UNPACK2(g0, g1, aG[r][0]); UNPACK2(g2, g3, aG[r][1]);

        p0 = fmaxf(p0 + bn4.x, 0.f); p1 = fmaxf(p1 + bn4.y, 0.f);
        p2 = fmaxf(p2 + bn4.z, 0.f); p3 = fmaxf(p3 + bn4.w, 0.f);
        g0 = 1.f / (1.f + __expf(-(g0 + bg4.x)));
        g1 = 1.f / (1.f + __expf(-(g1 + bg4.y)));
        g2 = 1.f / (1.f + __expf(-(g2 + bg4.z)));
        g3 = 1.f / (1.f + __expf(-(g3 + bg4.w)));

        float4 xin = X4[m * K4 + colBase];
        float4 y;
        y.x = g0 * xin.x + (1.f - g0) * p0;
        y.y = g1 * xin.y + (1.f - g1) * p1;
        y.z = g2 * xin.z + (1.f - g2) * p2;
        y.w = g3 * xin.w + (1.f - g3) * p3;

        ((float4*)Y)[m * K4 + colBase] = y;
        if (out2) {
            // d_out row stride 2H=1024 floats = 256 float4; fwd cols [0,512), bwd [512,1024)
            ((float4*)out2)[m * 256 + dir * 128 + colBase] = y;
        }
    }
}

// ---------------- launcher ----------------
extern "C" void kernel_launch(void* const* d_in, const int* in_sizes, int n_in,
                              void* d_out, int out_size)
{
    const float* in   = (const float*)d_in[0];
    // d_in[1] = masks (unused, matching reference)
    const float* fpad = (const float*)d_in[2];
    const float* bpad = (const float*)d_in[3];
    const float* fws  = (const float*)d_in[4];
    const float* bws  = (const float*)d_in[5];
    const float* fW   = (const float*)d_in[6];
    const float* fb   = (const float*)d_in[7];
    const float* bW   = (const float*)d_in[8];
    const float* bb   = (const float*)d_in[9];
    float* out = (float*)d_out;

    void* sym = nullptr;
    cudaGetSymbolAddress(&sym, g_buf);
    float* base = (float*)sym;
    float* b_[6];
    for (int i = 0; i < 6; ++i) b_[i] = base + (size_t)i * NBUF;

    dim3 cgrid(SS, BB);
    dim3 ggrid(8, MTOT / 128, 2);

    for (int l = 0; l < 2; ++l) {
        const float* xf = l ? b_[0] : in;
        const float* xb = l ? b_[1] : in;
        conv_kernel<<<cgrid, 128>>>(xf, xb,
                                    fpad + (size_t)l * 4 * HH, bpad + (size_t)l * 4 * HH,
                                    fws + l * 5, bws + l * 5,
                                    b_[2], b_[3]);

        size_t w0 = (size_t)(l * 2) * 1024 * 512;
        size_t w1 = (size_t)(l * 2 + 1) * 1024 * 512;

        // highway step 0: conv-out -> hw1-out
        hw_gemm<<<ggrid, 256>>>(b_[2], b_[3], fW + w0, bW + w0,
                                fb + (size_t)(l * 2) * 1024, bb + (size_t)(l * 2) * 1024,
                                b_[4], b_[5], nullptr);
        // highway step 1: hw1-out -> layer-out (+ d_out slice for this layer)
        hw_gemm<<<ggrid, 256>>>(b_[4], b_[5], fW + w1, bW + w1,
                                fb + (size_t)(l * 2 + 1) * 1024, bb + (size_t)(l * 2 + 1) * 1024,
                                b_[0], b_[1], out + (size_t)l * MTOT * 1024);
    }
}